// round 11
// baseline (speedup 1.0000x reference)
#include <cuda_runtime.h>
#include <cstdint>

// BilinearInteraction: out[b, p, :] = x[b, i_p, :] * (x[b, j_p, :] @ W)
//   x: [4096, 32, 64] f32, W: [64, 64] f32, out: [4096, 496, 64] f32
//   R10 compute frame + TMA bulk stores sized for 4 CTAs/SM (32 warps):
//   - per-warp double buffers of 1 KB (4 pairs), cp.async.bulk drains them
//   - removes STG.128 issue cost (12 cyc/instr = ~60% of L1 busy in R10)
//   - W via cp.async.bulk; padded xs; 96-wf GEMM; row-run chunking

#define NF 32
#define ED 64
#define NP 496
#define NTHREADS 256
#define NBATCH 4096
#define XSTR 17

// Dynamic smem layout (float4 units)
#define XS_OFF   0                        // 32 * 17            = 544
#define VS_OFF   544                      // 32 * 16            = 512
#define WS_OFF   1056                     // 64 * 16            = 1024
#define BUF_OFF  2080                     // 8 warps * 2 * 64   = 1024
#define MBAR_OFF (BUF_OFF + 8 * 128)      // 3104
#define SMEM_BYTES ((MBAR_OFF + 1) * 16)  // 49680 B -> 4 CTAs/SM

__device__ __forceinline__ unsigned smem_u32(const void* p) {
    unsigned a;
    asm("{ .reg .u64 t; cvta.to.shared.u64 t, %1; cvt.u32.u64 %0, t; }"
        : "=r"(a) : "l"(p));
    return a;
}

__global__ void __launch_bounds__(NTHREADS, 4)
bilinear_kernel(const float* __restrict__ x,
                const float* __restrict__ W,
                float* __restrict__ out)
{
    extern __shared__ float4 sm4[];
    unsigned long long* mbar = (unsigned long long*)(sm4 + MBAR_OFF);

    const int b   = blockIdx.x;
    const int tid = threadIdx.x;

    // ---- mbarrier init + W via 1D bulk load (async proxy) ----
    if (tid == 0) {
        asm volatile("mbarrier.init.shared.b64 [%0], 1;"
                     :: "r"(smem_u32(mbar)) : "memory");
    }
    __syncthreads();
    if (tid == 0) {
        const unsigned mb = smem_u32(mbar);
        asm volatile("mbarrier.arrive.expect_tx.shared.b64 _, [%0], %1;"
                     :: "r"(mb), "r"(16384u) : "memory");
        asm volatile(
            "cp.async.bulk.shared::cluster.global.mbarrier::complete_tx::bytes "
            "[%0], [%1], %2, [%3];"
            :: "r"(smem_u32(sm4 + WS_OFF)), "l"(W), "r"(16384u), "r"(mb)
            : "memory");
    }

    // ---- x prologue: padded copy ----
    {
        const float4* xg = (const float4*)(x + (size_t)b * (NF * ED));
#pragma unroll
        for (int k = 0; k < 2; k++) {
            const int idx = tid + k * NTHREADS;   // 0..511
            const int row = idx >> 4;
            const int col = idx & 15;
            sm4[XS_OFF + row * XSTR + col] = xg[idx];
        }
    }
    __syncthreads();

    // ---- wait for W (acquire) ----
    {
        const unsigned mb = smem_u32(mbar);
        unsigned done;
        asm volatile(
            "{\n\t.reg .pred p;\n\t"
            "mbarrier.try_wait.parity.acquire.cta.shared::cta.b64 p, [%1], 0;\n\t"
            "selp.b32 %0, 1, 0, p;\n\t}"
            : "=r"(done) : "r"(mb) : "memory");
        while (!done) {
            asm volatile(
                "{\n\t.reg .pred p;\n\t"
                "mbarrier.try_wait.parity.acquire.cta.shared::cta.b64 p, [%1], 0, 0x989680;\n\t"
                "selp.b32 %0, 1, 0, p;\n\t}"
                : "=r"(done) : "r"(mb) : "memory");
        }
    }

    // ---- GEMM (R10 layout): vid[f][e] = sum_d x[f][d] * W[d][e] ----
    {
        const int w    = tid >> 5;
        const int lane = tid & 31;
        const int wr   = w & 3;
        const int half = w >> 2;
        const int fi   = lane >> 3;
        const int ci   = lane & 7;
        const int f0   = 8 * wr + fi;
        const int c    = 8 * half + ci;

        float4 acc0 = make_float4(0.f, 0.f, 0.f, 0.f);
        float4 acc1 = make_float4(0.f, 0.f, 0.f, 0.f);

#pragma unroll 4
        for (int d4 = 0; d4 < 16; d4++) {
            const float4 xv0 = sm4[XS_OFF + f0 * XSTR + d4];
            const float4 xv1 = sm4[XS_OFF + (f0 + 4) * XSTR + d4];
#pragma unroll
            for (int dd = 0; dd < 4; dd++) {
                const float4 wv = sm4[WS_OFF + (4 * d4 + dd) * 16 + c];
                const float xa = (dd == 0) ? xv0.x : (dd == 1) ? xv0.y :
                                 (dd == 2) ? xv0.z : xv0.w;
                const float xb = (dd == 0) ? xv1.x : (dd == 1) ? xv1.y :
                                 (dd == 2) ? xv1.z : xv1.w;
                acc0.x = fmaf(xa, wv.x, acc0.x);
                acc0.y = fmaf(xa, wv.y, acc0.y);
                acc0.z = fmaf(xa, wv.z, acc0.z);
                acc0.w = fmaf(xa, wv.w, acc0.w);
                acc1.x = fmaf(xb, wv.x, acc1.x);
                acc1.y = fmaf(xb, wv.y, acc1.y);
                acc1.z = fmaf(xb, wv.z, acc1.z);
                acc1.w = fmaf(xb, wv.w, acc1.w);
            }
        }
        sm4[VS_OFF + f0 * 16 + c]       = acc0;
        sm4[VS_OFF + (f0 + 4) * 16 + c] = acc1;
    }
    __syncthreads();

    // ---- Write phase: rows {w, 30-w, 15-w, 15+w}; 4-pair (1 KB) chunks
    //      staged in per-warp double buffers, drained via cp.async.bulk ----
    {
        const int w    = tid >> 5;
        const int lane = tid & 31;
        const int v    = lane & 15;
        const int h    = lane >> 4;

        float4* out4 = (float4*)(out + (size_t)b * (NP * ED));
        float4* bufw = sm4 + BUF_OFF + w * 128;   // 2 x 64 f4 (2 x 1 KB)

        int rows[4];
        int nrows;
        if (w == 0) {
            rows[0] = 0; rows[1] = 30; rows[2] = 15; rows[3] = 0;
            nrows = 3;
        } else {
            rows[0] = w; rows[1] = 30 - w; rows[2] = 15 - w; rows[3] = 15 + w;
            nrows = 4;
        }

        int parity = 0;
        int issued = 0;

#pragma unroll
        for (int r = 0; r < 4; r++) {
            if (r >= nrows) break;
            const int i = rows[r];
            const float4 a = sm4[XS_OFF + i * XSTR + v];
            const int cnt  = 31 - i;
            const int p0   = (i * (63 - i)) >> 1;

            int done = 0;
            while (done < cnt) {
                const int take = (cnt - done < 4) ? (cnt - done) : 4;
                float4* bb = bufw + parity * 64;

                // reuse guard: this buffer's previous group must have drained
                if (issued >= 2) {
                    if (lane == 0)
                        asm volatile("cp.async.bulk.wait_group 1;" ::: "memory");
                }
                __syncwarp();

#pragma unroll
                for (int t = 0; t < 2; t++) {
                    const int q = 2 * t + h;          // pair idx in chunk
                    if (q < take) {
                        const int j = i + 1 + done + q;
                        const float4 cv = sm4[VS_OFF + j * 16 + v];
                        float4 rr;
                        rr.x = a.x * cv.x;
                        rr.y = a.y * cv.y;
                        rr.z = a.z * cv.z;
                        rr.w = a.w * cv.w;
                        bb[q * 16 + v] = rr;
                    }
                }
                __syncwarp();

                if (lane == 0) {
                    asm volatile("fence.proxy.async.shared::cta;" ::: "memory");
                    asm volatile(
                        "cp.async.bulk.global.shared::cta.bulk_group "
                        "[%0], [%1], %2;"
                        :: "l"(out4 + (p0 + done) * 16),
                           "r"(smem_u32(bb)),
                           "r"((unsigned)(take * 256))
                        : "memory");
                    asm volatile("cp.async.bulk.commit_group;" ::: "memory");
                }
                issued++;
                parity ^= 1;
                done += take;
            }
        }

        // drain all outstanding stores before exit
        if (lane == 0)
            asm volatile("cp.async.bulk.wait_group 0;" ::: "memory");
        __syncwarp();
    }
}

extern "C" void kernel_launch(void* const* d_in, const int* in_sizes, int n_in,
                              void* d_out, int out_size)
{
    const float* x = (const float*)d_in[0];
    const float* W = (const float*)d_in[1];
    float*       o = (float*)d_out;

    cudaFuncSetAttribute(bilinear_kernel,
                         cudaFuncAttributeMaxDynamicSharedMemorySize,
                         SMEM_BYTES);
    bilinear_kernel<<<NBATCH, NTHREADS, SMEM_BYTES>>>(x, W, o);
}